// round 13
// baseline (speedup 1.0000x reference)
#include <cuda_runtime.h>

#define FM 0xffffffffu

__device__ __forceinline__ float artanh_(float x) {
    x = fminf(fmaxf(x, -1.f + 1e-7f), 1.f - 1e-7f);
    return 0.5f * logf((1.f + x) / (1.f - x));
}

__device__ __forceinline__ float wred32(float v) {
#pragma unroll
    for (int o = 16; o; o >>= 1) v += __shfl_xor_sync(FM, v, o);
    return v;
}

__device__ __forceinline__ float gred16(float v) {
#pragma unroll
    for (int o = 8; o; o >>= 1) v += __shfl_xor_sync(FM, v, o);
    return v;
}

// Raw attention bilinear forms: E_raw[b][s] = self · Wr[b,s] · engh[b,s]
__device__ float g_Escratch[4096 * 16];
// Per-b arrival counter (cycles back to 0 every launch -> graph-replay safe)
__device__ unsigned int g_cnt[4096];

// ==================== Fused kernel ====================
// grid (B, 4), 128 threads. Stream phase: warp w of s-group sg contracts
// Wr[b, sg*4+w] (16KB) with raw self/engh vectors. The LAST of the 4 CTAs
// for batch b then runs the full epilogue for b on its warp 0, overlapped
// with other batches' streaming.
__global__ __launch_bounds__(128, 8)
void kgagg_fused(const float* __restrict__ g_self,   // (B,1,64)
                 const float* __restrict__ g_ungh,   // (B,16,64)
                 const float* __restrict__ g_engh,   // (B,1,16,64)
                 const float* __restrict__ g_item,   // (B,64)
                 const float* __restrict__ g_Wr,     // (B,1,16,64,64)
                 const float* __restrict__ g_Wui,    // (64,64)
                 const float* __restrict__ g_linW,   // (64,64)
                 const float* __restrict__ g_linb,   // (64,)
                 float* __restrict__ g_out)          // (B,1,64)
{
    const int b    = blockIdx.x;
    const int sg   = blockIdx.y;      // 0..3
    const int tid  = threadIdx.x;
    const int lane = tid & 31;
    const int warp = tid >> 5;        // 0..3

    // ---- stream-phase smem ----
    __shared__ float s_self[64];
    __shared__ float s_enghW[4][64];
    // ---- epilogue smem (single warp uses it; part of CTA footprint) ----
    __shared__ __align__(16) float sE[16][64];
    __shared__ __align__(16) float sU[16][64];
    __shared__ __align__(16) float sSelf[64], sIv[64];
    __shared__ float sS[12][16];
    __shared__ float sV[2][64];
    __shared__ int s_last;

    // ================= Phase 1: Wr stream =================
    if (tid < 64) s_self[tid] = g_self[b * 64 + tid];
#pragma unroll
    for (int i = tid; i < 256; i += 128)
        (&s_enghW[0][0])[i] = g_engh[(size_t)b * 1024 + sg * 256 + i];
    __syncthreads();

    const int l15 = lane & 15;
    const int hi  = lane >> 4;
    {
        const int si = sg * 4 + warp;
        const float4 a = *reinterpret_cast<const float4*>(&s_self[4 * l15]);
        const float4* p = reinterpret_cast<const float4*>(g_Wr)
                        + (size_t)b * 16384 + (size_t)si * 1024 + lane;
        float acc = 0.f;
#pragma unroll 8
        for (int i = 0; i < 32; i++) {
            float4 w = __ldcs(p + i * 32);
            acc += s_enghW[warp][2 * i + hi] * (w.x * a.x + w.y * a.y + w.z * a.z + w.w * a.w);
        }
        acc = wred32(acc);
        if (lane == 0) {
            g_Escratch[b * 16 + si] = acc;
            __threadfence();   // make visible at device scope before arrival
        }
    }
    __syncthreads();

    // ================= Arrival: last CTA of this b proceeds =================
    if (tid == 0) {
        unsigned int old = atomicAdd(&g_cnt[b], 1u);
        int last = (old == 3u);
        if (last) g_cnt[b] = 0u;   // reset for next launch/replay
        s_last = last;
    }
    __syncthreads();
    if (!s_last) return;
    __threadfence();               // acquire peer CTAs' Escratch stores
    if (warp != 0) return;

    // ================= Phase 2: warp-0 epilogue for batch b =================
    const float MIN  = 1e-15f;
    const float MAXN = 1.f - 0.004f;

    float (*E)[64] = sE;
    float (*U)[64] = sU;
    float* y2e  = sS[0];
    float* xye  = sS[1];
    float* y2u  = sS[2];
    float* xyu  = sS[3];
    float* elog = sS[4];   // reused as kae after softmax
    float* uelg = sS[5];   // reused as kbe after softmax
    float* att  = sS[6];
    float* uatt = sS[7];
    float* ce   = sS[8];
    float* cu   = sS[9];
    float* kau  = sS[10];
    float* kbu  = sS[11];
    float* vbuf0 = sV[0];  // imW, later o2
    float* vbuf1 = sV[1];  // mx

    // ---- load per-b tensors ----
    {
        const float4* e4 = reinterpret_cast<const float4*>(g_engh + (size_t)b * 1024);
        const float4* u4 = reinterpret_cast<const float4*>(g_ungh + (size_t)b * 1024);
#pragma unroll
        for (int i = lane; i < 256; i += 32) {
            reinterpret_cast<float4*>(&E[0][0])[i] = e4[i];
            reinterpret_cast<float4*>(&U[0][0])[i] = u4[i];
        }
        if (lane < 16)
            reinterpret_cast<float4*>(sSelf)[lane] =
                reinterpret_cast<const float4*>(g_self + (size_t)b * 64)[lane];
        else
            reinterpret_cast<float4*>(sIv)[lane - 16] =
                reinterpret_cast<const float4*>(g_item + (size_t)b * 64)[lane - 16];
    }
    __syncwarp();

    const float self0 = sSelf[lane], self1 = sSelf[lane + 32];
    const float iv0   = sIv[lane],   iv1   = sIv[lane + 32];

    // ---- base-point norms + logmap0 scalars ----
    const float x2self = wred32(self0 * self0 + self1 * self1);
    const float x2iv   = wred32(iv0 * iv0 + iv1 * iv1);
    float nself = fmaxf(sqrtf(x2self), MIN);
    const float fself = artanh_(nself) / nself;
    float niv = fmaxf(sqrtf(x2iv), MIN);
    const float fiv = artanh_(niv) / niv;

    float sfr[4], ivr[4];
#pragma unroll
    for (int j = 0; j < 4; j++) { sfr[j] = sSelf[l15 + 16 * j]; ivr[j] = sIv[l15 + 16 * j]; }

    // ---- per-s norms & dots (2 s per pass) ----
#pragma unroll
    for (int k = 0; k < 8; k++) {
        int s = 2 * k + hi;
        float pe = 0.f, pxe = 0.f, pu = 0.f, pxu = 0.f;
#pragma unroll
        for (int j = 0; j < 4; j++) {
            float ev = E[s][l15 + 16 * j]; pe += ev * ev; pxe += ev * sfr[j];
            float uv = U[s][l15 + 16 * j]; pu += uv * uv; pxu += uv * ivr[j];
        }
        pe = gred16(pe); pxe = gred16(pxe); pu = gred16(pu); pxu = gred16(pxu);
        if (l15 == 0) { y2e[s] = pe; xye[s] = pxe; y2u[s] = pu; xyu[s] = pxu; }
    }
    __syncwarp();

    // ---- entity logits: e[s] = fself * fe[s] * E_raw[b,s] ----
    if (lane < 16) {
        float ne = fmaxf(sqrtf(y2e[lane]), MIN);
        float fe = artanh_(ne) / ne;
        elog[lane] = fself * fe * __ldcg(&g_Escratch[b * 16 + lane]);
    }

    // ---- imW[r] = fiv * sum_d Wui[r,d]*iv[d]  (2 r per pass) ----
#pragma unroll
    for (int k = 0; k < 32; k++) {
        int r = 2 * k + hi;
        float v = 0.f;
#pragma unroll
        for (int j = 0; j < 4; j++) v += g_Wui[r * 64 + l15 + 16 * j] * ivr[j];
        v = gred16(v);
        if (l15 == 0) vbuf0[r] = fiv * v;
    }
    __syncwarp();

    // ---- u logits: ue[s] = fu[s] * dot(imW, ungh[s]) ----
    {
        float imwr[4];
#pragma unroll
        for (int j = 0; j < 4; j++) imwr[j] = vbuf0[l15 + 16 * j];
#pragma unroll
        for (int k = 0; k < 8; k++) {
            int s = 2 * k + hi;
            float p = 0.f;
#pragma unroll
            for (int j = 0; j < 4; j++) p += imwr[j] * U[s][l15 + 16 * j];
            p = gred16(p);
            if (l15 == 0) {
                float nu = fmaxf(sqrtf(y2u[s]), MIN);
                float fu = artanh_(nu) / nu;
                uelg[s] = fu * p;
            }
        }
    }
    __syncwarp();

    // ---- softmaxes over 16 ----
    {
        int s = lane & 15;
        float v1 = elog[s], v2 = uelg[s];
        float m1 = v1, m2 = v2;
#pragma unroll
        for (int o = 8; o; o >>= 1) {
            m1 = fmaxf(m1, __shfl_xor_sync(FM, m1, o));
            m2 = fmaxf(m2, __shfl_xor_sync(FM, m2, o));
        }
        float e1 = expf(v1 - m1), e2 = expf(v2 - m2);
        float s1 = e1, s2 = e2;
#pragma unroll
        for (int o = 8; o; o >>= 1) {
            s1 += __shfl_xor_sync(FM, s1, o);
            s2 += __shfl_xor_sync(FM, s2, o);
        }
        __syncwarp();
        if (lane < 16) { att[lane] = e1 / s1; uatt[lane] = e2 / s2; }
    }
    __syncwarp();

    // ---- mobius_add(-p, y) coefficients per s ----
    if (lane < 16) {
        int s = lane;
        float t2 = 2.f * xye[s];
        float den = fmaxf(1.f - t2 + x2self * y2e[s], MIN);
        elog[s] = -(1.f - t2 + y2e[s]) / den;   // kae
        uelg[s] = (1.f - x2self) / den;          // kbe
        float t2u = 2.f * xyu[s];
        float denu = fmaxf(1.f - t2u + x2iv * y2u[s], MIN);
        kau[s] = -(1.f - t2u + y2u[s]) / denu;
        kbu[s] = (1.f - x2iv) / denu;
    }
    __syncwarp();

    // ---- sub in place ----
#pragma unroll
    for (int s = 0; s < 16; s++) {
        float ka = elog[s], kb = uelg[s];
        E[s][lane]      = ka * self0 + kb * E[s][lane];
        E[s][lane + 32] = ka * self1 + kb * E[s][lane + 32];
        float ka2 = kau[s], kb2 = kbu[s];
        U[s][lane]      = ka2 * iv0 + kb2 * U[s][lane];
        U[s][lane + 32] = ka2 * iv1 + kb2 * U[s][lane + 32];
    }
    __syncwarp();

    // ---- sub norms -> attention-weighted logmap coefficients ----
#pragma unroll
    for (int k = 0; k < 8; k++) {
        int s = 2 * k + hi;
        float pe = 0.f, pu = 0.f;
#pragma unroll
        for (int j = 0; j < 4; j++) {
            float v = E[s][l15 + 16 * j]; pe += v * v;
            float u = U[s][l15 + 16 * j]; pu += u * u;
        }
        pe = gred16(pe); pu = gred16(pu);
        if (l15 == 0) {
            float lamE = fmaxf(2.f / (1.f - x2self), MIN);
            float sne = fmaxf(sqrtf(pe), MIN);
            ce[s] = att[s] * (2.f / lamE) * artanh_(sne) / sne;
            float lamU = fmaxf(2.f / (1.f - x2iv), MIN);
            float snu = fmaxf(sqrtf(pu), MIN);
            cu[s] = uatt[s] * (2.f / lamU) * artanh_(snu) / snu;
        }
    }
    __syncwarp();

    // ---- aggregate over s ----
    float a0 = 0.f, a1 = 0.f, b0 = 0.f, b1 = 0.f;
#pragma unroll
    for (int s = 0; s < 16; s++) {
        float c1 = ce[s], c2 = cu[s];
        a0 += c1 * E[s][lane]; a1 += c1 * E[s][lane + 32];
        b0 += c2 * U[s][lane]; b1 += c2 * U[s][lane + 32];
    }

    const float n2agge = wred32(a0 * a0 + a1 * a1);
    const float dsae   = wred32(self0 * a0 + self1 * a1);
    const float n2aggu = wred32(b0 * b0 + b1 * b1);
    const float diau   = wred32(iv0 * b0 + iv1 * b1);

    // ---- expmap at base + mobius_add(base, second) -> kg, ua ----
    float kg0, kg1, ua0, ua1;
    {
        float un  = fmaxf(sqrtf(n2agge), MIN);
        float lam = fmaxf(2.f / (1.f - x2self), MIN);
        float f   = tanhf(lam * un * 0.5f) / un;
        float xy = f * dsae, y2 = f * f * n2agge;
        float den = fmaxf(1.f + 2.f * xy + x2self * y2, MIN);
        kg0 = ((1.f + 2.f * xy + y2) * self0 + (1.f - x2self) * f * a0) / den;
        kg1 = ((1.f + 2.f * xy + y2) * self1 + (1.f - x2self) * f * a1) / den;

        float un2  = fmaxf(sqrtf(n2aggu), MIN);
        float lam2 = fmaxf(2.f / (1.f - x2iv), MIN);
        float f2   = tanhf(lam2 * un2 * 0.5f) / un2;
        float xy2 = f2 * diau, yy2 = f2 * f2 * n2aggu;
        float den2 = fmaxf(1.f + 2.f * xy2 + x2iv * yy2, MIN);
        ua0 = ((1.f + 2.f * xy2 + yy2) * iv0 + (1.f - x2iv) * f2 * b0) / den2;
        ua1 = ((1.f + 2.f * xy2 + yy2) * iv1 + (1.f - x2iv) * f2 * b1) / den2;
    }

    const float n2kg = wred32(kg0 * kg0 + kg1 * kg1);
    const float dskg = wred32(self0 * kg0 + self1 * kg1);
    const float n2ua = wred32(ua0 * ua0 + ua1 * ua1);

    // ---- o1 = mobius_add(self, kg) ----
    float o1_0, o1_1;
    {
        float den = fmaxf(1.f + 2.f * dskg + x2self * n2kg, MIN);
        o1_0 = ((1.f + 2.f * dskg + n2kg) * self0 + (1.f - x2self) * kg0) / den;
        o1_1 = ((1.f + 2.f * dskg + n2kg) * self1 + (1.f - x2self) * kg1) / den;
    }

    const float n2o1  = wred32(o1_0 * o1_0 + o1_1 * o1_1);
    const float do1ua = wred32(o1_0 * ua0 + o1_1 * ua1);

    // ---- o2 = mobius_add(o1, ua) ----
    float o2_0, o2_1;
    {
        float den = fmaxf(1.f + 2.f * do1ua + n2o1 * n2ua, MIN);
        o2_0 = ((1.f + 2.f * do1ua + n2ua) * o1_0 + (1.f - n2o1) * ua0) / den;
        o2_1 = ((1.f + 2.f * do1ua + n2ua) * o1_1 + (1.f - n2o1) * ua1) / den;
    }
    vbuf0[lane] = o2_0; vbuf0[lane + 32] = o2_1;
    __syncwarp();

    // ---- mx = lin_W @ o2 (2 r per pass) ----
    {
        float o2r[4];
#pragma unroll
        for (int j = 0; j < 4; j++) o2r[j] = vbuf0[l15 + 16 * j];
#pragma unroll
        for (int k = 0; k < 32; k++) {
            int r = 2 * k + hi;
            float v = 0.f;
#pragma unroll
            for (int j = 0; j < 4; j++) v += g_linW[r * 64 + l15 + 16 * j] * o2r[j];
            v = gred16(v);
            if (l15 == 0) vbuf1[r] = v;
        }
    }
    __syncwarp();
    const float mx0 = vbuf1[lane], mx1 = vbuf1[lane + 32];
    const float lb0 = g_linb[lane], lb1 = g_linb[lane + 32];

    const float mxn2 = wred32(mx0 * mx0 + mx1 * mx1);
    const float xn2  = wred32(o2_0 * o2_0 + o2_1 * o2_1);
    const float nb2  = wred32(lb0 * lb0 + lb1 * lb1);

    // ---- res = mobius_matvec scale; hb = expmap0(lin_b) ----
    float r0, r1, h0, h1;
    {
        float xn  = fmaxf(sqrtf(xn2), MIN);
        float mxn = fmaxf(sqrtf(mxn2), MIN);
        float f = tanhf(mxn / xn * artanh_(xn)) / mxn;
        r0 = f * mx0; r1 = f * mx1;
        float nb = fmaxf(sqrtf(nb2), MIN);
        float fb = tanhf(nb) / nb;
        h0 = fb * lb0; h1 = fb * lb1;
    }

    const float nres2 = wred32(r0 * r0 + r1 * r1);
    const float nhb2  = wred32(h0 * h0 + h1 * h1);
    const float drh   = wred32(r0 * h0 + r1 * h1);

    // ---- o3 = mobius_add(proj(res), proj(hb)) ----
    float o3_0, o3_1;
    {
        float nr = fmaxf(sqrtf(nres2), MIN);
        float pr = (nr > MAXN) ? MAXN / nr : 1.f;
        float nh = fmaxf(sqrtf(nhb2), MIN);
        float ph = (nh > MAXN) ? MAXN / nh : 1.f;
        float x2 = pr * pr * nres2;
        float y2 = ph * ph * nhb2;
        float xy = pr * ph * drh;
        float den = fmaxf(1.f + 2.f * xy + x2 * y2, MIN);
        o3_0 = ((1.f + 2.f * xy + y2) * pr * r0 + (1.f - x2) * ph * h0) / den;
        o3_1 = ((1.f + 2.f * xy + y2) * pr * r1 + (1.f - x2) * ph * h1) / den;
    }

    const float n2o3 = wred32(o3_0 * o3_0 + o3_1 * o3_1);

    // ---- t = tanh(logmap0(proj(o3))) ----
    float t0, t1;
    {
        float n3 = fmaxf(sqrtf(n2o3), MIN);
        float p3 = (n3 > MAXN) ? MAXN / n3 : 1.f;
        float np = fmaxf(p3 * n3, MIN);
        float fL = artanh_(np) / np;
        t0 = tanhf(fL * p3 * o3_0);
        t1 = tanhf(fL * p3 * o3_1);
    }

    const float n2t = wred32(t0 * t0 + t1 * t1);

    // ---- out = expmap0(t) ----
    {
        float nt = fmaxf(sqrtf(n2t), MIN);
        float f = tanhf(nt) / nt;
        g_out[(size_t)b * 64 + lane]      = f * t0;
        g_out[(size_t)b * 64 + lane + 32] = f * t1;
    }
}

extern "C" void kernel_launch(void* const* d_in, const int* in_sizes, int n_in,
                              void* d_out, int out_size) {
    // inputs (metadata order): self_vectors, ngh_user_vectors, ngh_entity_vectors,
    //                          item_embeddings, Wr, W_ui, lin_W, lin_b
    int B = in_sizes[0] / 64;

    dim3 g(B, 4);
    kgagg_fused<<<g, 128>>>(
        (const float*)d_in[0],  // self_vectors
        (const float*)d_in[1],  // ngh_user_vectors
        (const float*)d_in[2],  // ngh_entity_vectors
        (const float*)d_in[3],  // item_embeddings
        (const float*)d_in[4],  // Wr
        (const float*)d_in[5],  // W_ui
        (const float*)d_in[6],  // lin_W
        (const float*)d_in[7],  // lin_b
        (float*)d_out);
}

// round 14
// speedup vs baseline: 1.1100x; 1.1100x over previous
#include <cuda_runtime.h>

#define FM 0xffffffffu

__device__ __forceinline__ float artanh_(float x) {
    x = fminf(fmaxf(x, -1.f + 1e-7f), 1.f - 1e-7f);
    return 0.5f * logf((1.f + x) / (1.f - x));
}

__device__ __forceinline__ float wred32(float v) {
#pragma unroll
    for (int o = 16; o; o >>= 1) v += __shfl_xor_sync(FM, v, o);
    return v;
}

__device__ __forceinline__ float gred16(float v) {
#pragma unroll
    for (int o = 8; o; o >>= 1) v += __shfl_xor_sync(FM, v, o);
    return v;
}

// Raw attention bilinear forms: E_raw[b][s] = self · Wr[b,s] · engh[b,s]
__device__ float g_Escratch[4096 * 16];

// ==================== Kernel A: pure Wr stream (proven ~71us) ====================
__global__ __launch_bounds__(128)
void wr_stream_kernel(const float* __restrict__ g_self,   // (B,1,64)
                      const float* __restrict__ g_engh,   // (B,1,16,64)
                      const float* __restrict__ g_Wr)     // (B,1,16,64,64)
{
    const int b    = blockIdx.x;
    const int sg   = blockIdx.y;      // 0..3
    const int tid  = threadIdx.x;
    const int lane = tid & 31;
    const int warp = tid >> 5;        // 0..3

    __shared__ float s_self[64];
    __shared__ float s_engh[4][64];

    if (tid < 64) s_self[tid] = g_self[b * 64 + tid];
#pragma unroll
    for (int i = tid; i < 256; i += 128)
        (&s_engh[0][0])[i] = g_engh[(size_t)b * 1024 + sg * 256 + i];
    __syncthreads();

    const int si  = sg * 4 + warp;
    const int l15 = lane & 15;
    const int hi  = lane >> 4;
    const float4 a = *reinterpret_cast<const float4*>(&s_self[4 * l15]);
    const float4* p = reinterpret_cast<const float4*>(g_Wr)
                    + (size_t)b * 16384 + (size_t)si * 1024 + lane;
    float acc = 0.f;
#pragma unroll 8
    for (int i = 0; i < 32; i++) {
        float4 w = __ldcs(p + i * 32);
        acc += s_engh[warp][2 * i + hi] * (w.x * a.x + w.y * a.y + w.z * a.z + w.w * a.w);
    }
    acc = wred32(acc);
    if (lane == 0) g_Escratch[b * 16 + si] = acc;
}

// ==================== Kernel B: warp-per-b epilogue, v2 ====================
// No neighbor tiles in smem: engh/ungh streamed from global (L1/L2-hot) in
// three float4 passes. Sub vectors are NEVER materialized:
//   |sub|^2 = ka^2*x2 + 2*ka*kb*xy + kb^2*y2   (scalars)
//   agg     = (sum ce*ka)*base + sum (ce*kb)*ngh[s]
__global__ __launch_bounds__(128, 8)
void kgagg_epilogue(const float* __restrict__ g_self,   // (B,1,64)
                    const float* __restrict__ g_ungh,   // (B,16,64)
                    const float* __restrict__ g_engh,   // (B,1,16,64)
                    const float* __restrict__ g_item,   // (B,64)
                    const float* __restrict__ g_Wui,    // (64,64)
                    const float* __restrict__ g_linW,   // (64,64)
                    const float* __restrict__ g_linb,   // (64,)
                    float* __restrict__ g_out,          // (B,1,64)
                    int B)
{
    __shared__ __align__(16) float sSelf[4][64], sIv[4][64];
    __shared__ float sS[4][12][16];   // per-s scalar arrays
    __shared__ __align__(16) float sV[4][2][64];

    const int warp = threadIdx.x >> 5;
    const int lane = threadIdx.x & 31;
    const int b    = blockIdx.x * 4 + warp;
    if (b >= B) return;

    const int l15 = lane & 15;
    const int hi  = lane >> 4;
    const float MIN  = 1e-15f;
    const float MAXN = 1.f - 0.004f;

    float* Sf   = sSelf[warp];
    float* Iv   = sIv[warp];
    float* y2e  = sS[warp][0];
    float* xye  = sS[warp][1];
    float* y2u  = sS[warp][2];
    float* xyu  = sS[warp][3];
    float* elog = sS[warp][4];
    float* uelg = sS[warp][5];
    float* att  = sS[warp][6];
    float* uatt = sS[warp][7];
    float* wea  = sS[warp][8];    // ce*ka  (entity)
    float* web  = sS[warp][9];    // ce*kb
    float* wua  = sS[warp][10];   // cu*ka  (user)
    float* wub  = sS[warp][11];   // cu*kb
    float* vbuf0 = sV[warp][0];   // imW, later o2
    float* vbuf1 = sV[warp][1];   // mx

    const float* Eg = g_engh + (size_t)b * 1024;
    const float* Ug = g_ungh + (size_t)b * 1024;

    // ---- load base points ----
    if (lane < 16)
        reinterpret_cast<float4*>(Sf)[lane] =
            reinterpret_cast<const float4*>(g_self + (size_t)b * 64)[lane];
    else
        reinterpret_cast<float4*>(Iv)[lane - 16] =
            reinterpret_cast<const float4*>(g_item + (size_t)b * 64)[lane - 16];
    __syncwarp();

    const float self0 = Sf[lane], self1 = Sf[lane + 32];
    const float iv0   = Iv[lane], iv1   = Iv[lane + 32];

    const float x2self = wred32(self0 * self0 + self1 * self1);
    const float x2iv   = wred32(iv0 * iv0 + iv1 * iv1);
    float nself = fmaxf(sqrtf(x2self), MIN);
    const float fself = artanh_(nself) / nself;
    float niv = fmaxf(sqrtf(x2iv), MIN);
    const float fiv = artanh_(niv) / niv;

    float sfr[4], ivr[4];
#pragma unroll
    for (int j = 0; j < 4; j++) { sfr[j] = Sf[4 * l15 + j]; ivr[j] = Iv[4 * l15 + j]; }

    // ---- Pass 1: per-s norms & dots (2 s per pass, float4 from global) ----
#pragma unroll
    for (int k = 0; k < 8; k++) {
        int s = 2 * k + hi;
        float4 e = __ldg(reinterpret_cast<const float4*>(Eg + s * 64 + 4 * l15));
        float4 u = __ldg(reinterpret_cast<const float4*>(Ug + s * 64 + 4 * l15));
        float pe  = e.x * e.x + e.y * e.y + e.z * e.z + e.w * e.w;
        float pxe = e.x * sfr[0] + e.y * sfr[1] + e.z * sfr[2] + e.w * sfr[3];
        float pu  = u.x * u.x + u.y * u.y + u.z * u.z + u.w * u.w;
        float pxu = u.x * ivr[0] + u.y * ivr[1] + u.z * ivr[2] + u.w * ivr[3];
        pe = gred16(pe); pxe = gred16(pxe); pu = gred16(pu); pxu = gred16(pxu);
        if (l15 == 0) { y2e[s] = pe; xye[s] = pxe; y2u[s] = pu; xyu[s] = pxu; }
    }
    __syncwarp();

    // ---- entity logits ----
    if (lane < 16) {
        float ne = fmaxf(sqrtf(y2e[lane]), MIN);
        float fe = artanh_(ne) / ne;
        elog[lane] = fself * fe * g_Escratch[b * 16 + lane];
    }

    // ---- Pass 2: imW[r] = fiv * Wui[r,:]·iv  (2 r per pass) ----
#pragma unroll
    for (int k = 0; k < 32; k++) {
        int r = 2 * k + hi;
        float4 w = __ldg(reinterpret_cast<const float4*>(g_Wui + r * 64 + 4 * l15));
        float v = w.x * ivr[0] + w.y * ivr[1] + w.z * ivr[2] + w.w * ivr[3];
        v = gred16(v);
        if (l15 == 0) vbuf0[r] = fiv * v;
    }
    __syncwarp();

    // ---- Pass 3: u logits ----
    {
        float imwr[4];
#pragma unroll
        for (int j = 0; j < 4; j++) imwr[j] = vbuf0[4 * l15 + j];
#pragma unroll
        for (int k = 0; k < 8; k++) {
            int s = 2 * k + hi;
            float4 u = __ldg(reinterpret_cast<const float4*>(Ug + s * 64 + 4 * l15));
            float p = u.x * imwr[0] + u.y * imwr[1] + u.z * imwr[2] + u.w * imwr[3];
            p = gred16(p);
            if (l15 == 0) {
                float nu = fmaxf(sqrtf(y2u[s]), MIN);
                float fu = artanh_(nu) / nu;
                uelg[s] = fu * p;
            }
        }
    }
    __syncwarp();

    // ---- softmaxes over 16 ----
    {
        int s = lane & 15;
        float v1 = elog[s], v2 = uelg[s];
        float m1 = v1, m2 = v2;
#pragma unroll
        for (int o = 8; o; o >>= 1) {
            m1 = fmaxf(m1, __shfl_xor_sync(FM, m1, o));
            m2 = fmaxf(m2, __shfl_xor_sync(FM, m2, o));
        }
        float e1 = expf(v1 - m1), e2 = expf(v2 - m2);
        float s1 = e1, s2 = e2;
#pragma unroll
        for (int o = 8; o; o >>= 1) {
            s1 += __shfl_xor_sync(FM, s1, o);
            s2 += __shfl_xor_sync(FM, s2, o);
        }
        __syncwarp();
        if (lane < 16) { att[lane] = e1 / s1; uatt[lane] = e2 / s2; }
    }
    __syncwarp();

    // ---- mobius_add(-p,y) coeffs + analytic sub norms + logmap weights ----
    if (lane < 16) {
        int s = lane;
        // entity
        float t2 = 2.f * xye[s];
        float den = fmaxf(1.f - t2 + x2self * y2e[s], MIN);
        float ka = -(1.f - t2 + y2e[s]) / den;
        float kb = (1.f - x2self) / den;
        float sn2 = ka * ka * x2self + 2.f * ka * kb * xye[s] + kb * kb * y2e[s];
        float sne = fmaxf(sqrtf(sn2), MIN);
        float ce = att[s] * (1.f - x2self) * artanh_(sne) / sne;
        wea[s] = ce * ka;
        web[s] = ce * kb;
        // user
        float t2u = 2.f * xyu[s];
        float denu = fmaxf(1.f - t2u + x2iv * y2u[s], MIN);
        float ka2 = -(1.f - t2u + y2u[s]) / denu;
        float kb2 = (1.f - x2iv) / denu;
        float sn2u = ka2 * ka2 * x2iv + 2.f * ka2 * kb2 * xyu[s] + kb2 * kb2 * y2u[s];
        float snu = fmaxf(sqrtf(sn2u), MIN);
        float cu = uatt[s] * (1.f - x2iv) * artanh_(snu) / snu;
        wua[s] = cu * ka2;
        wub[s] = cu * kb2;
    }
    __syncwarp();

    // ---- Pass 4: aggregates (weighted sums over s, straight from global) ----
    float a0 = 0.f, a1 = 0.f, b0 = 0.f, b1 = 0.f;
    float ska = 0.f, sku = 0.f;
#pragma unroll
    for (int s = 0; s < 16; s++) {
        float wb = web[s], wu2 = wub[s];
        a0 += wb * __ldg(Eg + s * 64 + lane);
        a1 += wb * __ldg(Eg + s * 64 + lane + 32);
        b0 += wu2 * __ldg(Ug + s * 64 + lane);
        b1 += wu2 * __ldg(Ug + s * 64 + lane + 32);
        ska += wea[s];
        sku += wua[s];
    }
    a0 += ska * self0; a1 += ska * self1;
    b0 += sku * iv0;   b1 += sku * iv1;

    const float n2agge = wred32(a0 * a0 + a1 * a1);
    const float dsae   = wred32(self0 * a0 + self1 * a1);
    const float n2aggu = wred32(b0 * b0 + b1 * b1);
    const float diau   = wred32(iv0 * b0 + iv1 * b1);

    // ---- expmap at base + mobius_add(base, second) -> kg, ua ----
    float kg0, kg1, ua0, ua1;
    {
        float un  = fmaxf(sqrtf(n2agge), MIN);
        float lam = fmaxf(2.f / (1.f - x2self), MIN);
        float f   = tanhf(lam * un * 0.5f) / un;
        float xy = f * dsae, y2 = f * f * n2agge;
        float den = fmaxf(1.f + 2.f * xy + x2self * y2, MIN);
        kg0 = ((1.f + 2.f * xy + y2) * self0 + (1.f - x2self) * f * a0) / den;
        kg1 = ((1.f + 2.f * xy + y2) * self1 + (1.f - x2self) * f * a1) / den;

        float un2  = fmaxf(sqrtf(n2aggu), MIN);
        float lam2 = fmaxf(2.f / (1.f - x2iv), MIN);
        float f2   = tanhf(lam2 * un2 * 0.5f) / un2;
        float xy2 = f2 * diau, yy2 = f2 * f2 * n2aggu;
        float den2 = fmaxf(1.f + 2.f * xy2 + x2iv * yy2, MIN);
        ua0 = ((1.f + 2.f * xy2 + yy2) * iv0 + (1.f - x2iv) * f2 * b0) / den2;
        ua1 = ((1.f + 2.f * xy2 + yy2) * iv1 + (1.f - x2iv) * f2 * b1) / den2;
    }

    const float n2kg = wred32(kg0 * kg0 + kg1 * kg1);
    const float dskg = wred32(self0 * kg0 + self1 * kg1);
    const float n2ua = wred32(ua0 * ua0 + ua1 * ua1);

    // ---- o1 = mobius_add(self, kg) ----
    float o1_0, o1_1;
    {
        float den = fmaxf(1.f + 2.f * dskg + x2self * n2kg, MIN);
        o1_0 = ((1.f + 2.f * dskg + n2kg) * self0 + (1.f - x2self) * kg0) / den;
        o1_1 = ((1.f + 2.f * dskg + n2kg) * self1 + (1.f - x2self) * kg1) / den;
    }

    const float n2o1  = wred32(o1_0 * o1_0 + o1_1 * o1_1);
    const float do1ua = wred32(o1_0 * ua0 + o1_1 * ua1);

    // ---- o2 = mobius_add(o1, ua) ----
    float o2_0, o2_1;
    {
        float den = fmaxf(1.f + 2.f * do1ua + n2o1 * n2ua, MIN);
        o2_0 = ((1.f + 2.f * do1ua + n2ua) * o1_0 + (1.f - n2o1) * ua0) / den;
        o2_1 = ((1.f + 2.f * do1ua + n2ua) * o1_1 + (1.f - n2o1) * ua1) / den;
    }
    vbuf0[lane] = o2_0; vbuf0[lane + 32] = o2_1;
    __syncwarp();

    // ---- mx = lin_W @ o2 (2 r per pass) ----
    {
        float o2r[4];
#pragma unroll
        for (int j = 0; j < 4; j++) o2r[j] = vbuf0[4 * l15 + j];
#pragma unroll
        for (int k = 0; k < 32; k++) {
            int r = 2 * k + hi;
            float4 w = __ldg(reinterpret_cast<const float4*>(g_linW + r * 64 + 4 * l15));
            float v = w.x * o2r[0] + w.y * o2r[1] + w.z * o2r[2] + w.w * o2r[3];
            v = gred16(v);
            if (l15 == 0) vbuf1[r] = v;
        }
    }
    __syncwarp();
    const float mx0 = vbuf1[lane], mx1 = vbuf1[lane + 32];
    const float lb0 = __ldg(g_linb + lane), lb1 = __ldg(g_linb + lane + 32);

    const float mxn2 = wred32(mx0 * mx0 + mx1 * mx1);
    const float xn2  = wred32(o2_0 * o2_0 + o2_1 * o2_1);
    const float nb2  = wred32(lb0 * lb0 + lb1 * lb1);

    // ---- res = mobius_matvec scale; hb = expmap0(lin_b) ----
    float r0, r1, h0, h1;
    {
        float xn  = fmaxf(sqrtf(xn2), MIN);
        float mxn = fmaxf(sqrtf(mxn2), MIN);
        float f = tanhf(mxn / xn * artanh_(xn)) / mxn;
        r0 = f * mx0; r1 = f * mx1;
        float nb = fmaxf(sqrtf(nb2), MIN);
        float fb = tanhf(nb) / nb;
        h0 = fb * lb0; h1 = fb * lb1;
    }

    const float nres2 = wred32(r0 * r0 + r1 * r1);
    const float nhb2  = wred32(h0 * h0 + h1 * h1);
    const float drh   = wred32(r0 * h0 + r1 * h1);

    // ---- o3 = mobius_add(proj(res), proj(hb)) ----
    float o3_0, o3_1;
    {
        float nr = fmaxf(sqrtf(nres2), MIN);
        float pr = (nr > MAXN) ? MAXN / nr : 1.f;
        float nh = fmaxf(sqrtf(nhb2), MIN);
        float ph = (nh > MAXN) ? MAXN / nh : 1.f;
        float x2 = pr * pr * nres2;
        float y2 = ph * ph * nhb2;
        float xy = pr * ph * drh;
        float den = fmaxf(1.f + 2.f * xy + x2 * y2, MIN);
        o3_0 = ((1.f + 2.f * xy + y2) * pr * r0 + (1.f - x2) * ph * h0) / den;
        o3_1 = ((1.f + 2.f * xy + y2) * pr * r1 + (1.f - x2) * ph * h1) / den;
    }

    const float n2o3 = wred32(o3_0 * o3_0 + o3_1 * o3_1);

    // ---- t = tanh(logmap0(proj(o3))) ----
    float t0, t1;
    {
        float n3 = fmaxf(sqrtf(n2o3), MIN);
        float p3 = (n3 > MAXN) ? MAXN / n3 : 1.f;
        float np = fmaxf(p3 * n3, MIN);
        float fL = artanh_(np) / np;
        t0 = tanhf(fL * p3 * o3_0);
        t1 = tanhf(fL * p3 * o3_1);
    }

    const float n2t = wred32(t0 * t0 + t1 * t1);

    // ---- out = expmap0(t) ----
    {
        float nt = fmaxf(sqrtf(n2t), MIN);
        float f = tanhf(nt) / nt;
        g_out[(size_t)b * 64 + lane]      = f * t0;
        g_out[(size_t)b * 64 + lane + 32] = f * t1;
    }
}

extern "C" void kernel_launch(void* const* d_in, const int* in_sizes, int n_in,
                              void* d_out, int out_size) {
    // inputs (metadata order): self_vectors, ngh_user_vectors, ngh_entity_vectors,
    //                          item_embeddings, Wr, W_ui, lin_W, lin_b
    int B = in_sizes[0] / 64;

    dim3 gA(B, 4);
    wr_stream_kernel<<<gA, 128>>>(
        (const float*)d_in[0],  // self_vectors
        (const float*)d_in[2],  // ngh_entity_vectors
        (const float*)d_in[4]); // Wr

    kgagg_epilogue<<<(B + 3) / 4, 128>>>(
        (const float*)d_in[0],  // self_vectors
        (const float*)d_in[1],  // ngh_user_vectors
        (const float*)d_in[2],  // ngh_entity_vectors
        (const float*)d_in[3],  // item_embeddings
        (const float*)d_in[5],  // W_ui
        (const float*)d_in[6],  // lin_W
        (const float*)d_in[7],  // lin_b
        (float*)d_out,
        B);
}